// round 1
// baseline (speedup 1.0000x reference)
#include <cuda_runtime.h>

#define N 2048
#define NB 8
#define NN (N * N)

// Scratch powers of A (device globals: allocation-free per harness rules)
__device__ float g_A2[(size_t)NB * NN];
__device__ float g_A3[(size_t)NB * NN];
__device__ float g_A4[(size_t)NB * NN];
// Diagonals d2..d8 : g_D[p][b][n], p = t-2
__device__ float g_D[7 * NB * N];

// ---------------------------------------------------------------------------
// Batched SGEMM: C = X @ Y, all [NB][N][N] row-major.
// 128x128 block tile, BK=8, 8x8 per-thread microtile, 256 threads.
// ---------------------------------------------------------------------------
__global__ __launch_bounds__(256) void sgemm_kernel(
    const float* __restrict__ X, const float* __restrict__ Y,
    float* __restrict__ C)
{
    constexpr int BM = 128, BN = 128, BK = 8, TM = 8, TN = 8;
    const int b = blockIdx.z;
    const float* Xb = X + (size_t)b * NN;
    const float* Yb = Y + (size_t)b * NN;
    float* Cb = C + (size_t)b * NN;

    __shared__ float As[BK][BM];
    __shared__ float Bs[BK][BN];

    const int tid = threadIdx.x;
    const int bm = blockIdx.y * BM;
    const int bn = blockIdx.x * BN;

    const int tr = (tid / 16) * TM;   // microtile row base within block
    const int tc = (tid % 16) * TN;   // microtile col base within block

    // A tile load: 128 rows x 8 cols, one float4 per thread
    const int arow = tid >> 1;
    const int acol = (tid & 1) * 4;
    // B tile load: 8 rows x 128 cols, one float4 per thread
    const int brl = tid >> 5;
    const int bcl = (tid & 31) * 4;

    float acc[TM][TN];
#pragma unroll
    for (int i = 0; i < TM; i++)
#pragma unroll
        for (int j = 0; j < TN; j++) acc[i][j] = 0.0f;

    for (int k0 = 0; k0 < N; k0 += BK) {
        float4 av = *(const float4*)(Xb + (size_t)(bm + arow) * N + k0 + acol);
        As[acol + 0][arow] = av.x;
        As[acol + 1][arow] = av.y;
        As[acol + 2][arow] = av.z;
        As[acol + 3][arow] = av.w;
        float4 bv = *(const float4*)(Yb + (size_t)(k0 + brl) * N + bn + bcl);
        *(float4*)&Bs[brl][bcl] = bv;
        __syncthreads();

#pragma unroll
        for (int kk = 0; kk < BK; kk++) {
            float ar[TM], br[TN];
#pragma unroll
            for (int i = 0; i < TM; i++) ar[i] = As[kk][tr + i];
#pragma unroll
            for (int j = 0; j < TN; j++) br[j] = Bs[kk][tc + j];
#pragma unroll
            for (int i = 0; i < TM; i++)
#pragma unroll
                for (int j = 0; j < TN; j++) acc[i][j] = fmaf(ar[i], br[j], acc[i][j]);
        }
        __syncthreads();
    }

#pragma unroll
    for (int i = 0; i < TM; i++) {
        float* crow = Cb + (size_t)(bm + tr + i) * N + bn + tc;
        *(float4*)(crow + 0) = make_float4(acc[i][0], acc[i][1], acc[i][2], acc[i][3]);
        *(float4*)(crow + 4) = make_float4(acc[i][4], acc[i][5], acc[i][6], acc[i][7]);
    }
}

// ---------------------------------------------------------------------------
// Diagonal pair-products: for each (b, n) compute
//   d2=<A,A> d3=<A2,A> d4=<A2,A2> d5=<A4,A> d6=<A4,A2> d7=<A4,A3> d8=<A4,A4>
// where <X,Y>[n] = sum_k X[n,k] * Y[k,n].
// Block: 256 threads, 32 n-values; tiles of 32 k. All loads coalesced; column
// operands are transposed through shared memory.
// ---------------------------------------------------------------------------
__global__ __launch_bounds__(256) void diag_kernel(const float* __restrict__ A)
{
    const int b = blockIdx.y;
    const int n0 = blockIdx.x * 32;
    const float* Ab  = A    + (size_t)b * NN;
    const float* A2b = g_A2 + (size_t)b * NN;
    const float* A3b = g_A3 + (size_t)b * NN;
    const float* A4b = g_A4 + (size_t)b * NN;

    __shared__ float xr[3][32][33];   // rows of A, A2, A4 : [m][n_local][k_local]
    __shared__ float yc[4][32][33];   // cols of A, A2, A3, A4 (transposed): [m][n_local][k_local]
    __shared__ float red[7][8][32];

    const int tid = threadIdx.x;
    const int r = tid >> 5;    // 0..7
    const int c = tid & 31;    // 0..31

    float acc[7];
#pragma unroll
    for (int p = 0; p < 7; p++) acc[p] = 0.0f;

    for (int k0 = 0; k0 < N; k0 += 32) {
#pragma unroll
        for (int l = 0; l < 4; l++) {
            const int i = r + 8 * l;
            // row tiles: X[n0+i][k0+c]
            xr[0][i][c] = Ab [(size_t)(n0 + i) * N + k0 + c];
            xr[1][i][c] = A2b[(size_t)(n0 + i) * N + k0 + c];
            xr[2][i][c] = A4b[(size_t)(n0 + i) * N + k0 + c];
            // col tiles (transposed store): Y[k0+i][n0+c] -> yc[m][c][i]
            yc[0][c][i] = Ab [(size_t)(k0 + i) * N + n0 + c];
            yc[1][c][i] = A2b[(size_t)(k0 + i) * N + n0 + c];
            yc[2][c][i] = A3b[(size_t)(k0 + i) * N + n0 + c];
            yc[3][c][i] = A4b[(size_t)(k0 + i) * N + n0 + c];
        }
        __syncthreads();

#pragma unroll
        for (int q = 0; q < 4; q++) {
            const int kk = r * 4 + q;
            const float a   = xr[0][c][kk];
            const float a2  = xr[1][c][kk];
            const float a4  = xr[2][c][kk];
            const float ca  = yc[0][c][kk];
            const float ca2 = yc[1][c][kk];
            const float ca3 = yc[2][c][kk];
            const float ca4 = yc[3][c][kk];
            acc[0] = fmaf(a,  ca,  acc[0]);   // d2
            acc[1] = fmaf(a2, ca,  acc[1]);   // d3
            acc[2] = fmaf(a2, ca2, acc[2]);   // d4
            acc[3] = fmaf(a4, ca,  acc[3]);   // d5
            acc[4] = fmaf(a4, ca2, acc[4]);   // d6
            acc[5] = fmaf(a4, ca3, acc[5]);   // d7
            acc[6] = fmaf(a4, ca4, acc[6]);   // d8
        }
        __syncthreads();
    }

#pragma unroll
    for (int p = 0; p < 7; p++) red[p][r][c] = acc[p];
    __syncthreads();

    if (r == 0) {
#pragma unroll
        for (int p = 0; p < 7; p++) {
            float s = 0.0f;
#pragma unroll
            for (int rr = 0; rr < 8; rr++) s += red[p][rr][c];
            g_D[(size_t)p * NB * N + (size_t)b * N + n0 + c] = s;
        }
    }
}

// ---------------------------------------------------------------------------
// Combine: out[b,n,c] = h[0,c] + h[1,c]*A[b,n,n] + sum_{t=2..8} h[t,c]*D[t-2,b,n]
// ---------------------------------------------------------------------------
__global__ __launch_bounds__(256) void combine_kernel(
    const float* __restrict__ A, const float* __restrict__ h,
    float* __restrict__ out)
{
    const int idx = blockIdx.x * blockDim.x + threadIdx.x;
    if (idx >= NB * N * 64) return;
    const int c = idx & 63;
    const int n = (idx >> 6) & (N - 1);
    const int b = idx >> 17;   // / (64*2048)

    const float d1 = A[(size_t)b * NN + (size_t)n * N + n];
    float v = h[c] + h[64 + c] * d1;
#pragma unroll
    for (int t = 2; t <= 8; t++) {
        const float dt = g_D[(size_t)(t - 2) * NB * N + (size_t)b * N + n];
        v = fmaf(h[t * 64 + c], dt, v);
    }
    out[idx] = v;
}

// ---------------------------------------------------------------------------
extern "C" void kernel_launch(void* const* d_in, const int* in_sizes, int n_in,
                              void* d_out, int out_size)
{
    const float* A = (const float*)d_in[0];   // [8, 2048, 2048]
    const float* h = (const float*)d_in[1];   // [9, 64]
    float* out = (float*)d_out;               // [8, 2048, 64]

    float* A2;  cudaGetSymbolAddress((void**)&A2, g_A2);
    float* A3;  cudaGetSymbolAddress((void**)&A3, g_A3);
    float* A4;  cudaGetSymbolAddress((void**)&A4, g_A4);

    dim3 gg(N / 128, N / 128, NB);
    // A2 = A @ A
    sgemm_kernel<<<gg, 256>>>(A, A, A2);
    // A3 = A2 @ A
    sgemm_kernel<<<gg, 256>>>(A2, A, A3);
    // A4 = A2 @ A2
    sgemm_kernel<<<gg, 256>>>(A2, A2, A4);

    dim3 gd(N / 32, NB);
    diag_kernel<<<gd, 256>>>(A);

    const int total = NB * N * 64;
    combine_kernel<<<(total + 255) / 256, 256>>>(A, h, out);
}

// round 3
// speedup vs baseline: 2.3164x; 2.3164x over previous
#include <cuda_runtime.h>
#include <cuda_bf16.h>
#include <cstdint>

#define N 2048
#define NB 8
#define NN (N * N)

// ---------------- GEMM tiling ----------------
#define BM 128
#define BN 128
#define BK 32
#define NT (N / BK)            // 64 k-tiles
#define ROWB 80                // padded row bytes (40 bf16, conflict-free LDSM)
#define TILEB (128 * ROWB)     // 10240 B per operand tile
#define STAGEB (4 * TILEB)     // Ah, Al, Bh, Bl
#define SMEM_GEMM (3 * STAGEB) // 3-stage pipeline = 122880 B

// ---------------- device scratch ----------------
__device__ float g_A2[(size_t)NB * NN];
__device__ float g_A3[(size_t)NB * NN];
__device__ float g_A4[(size_t)NB * NN];
__device__ __nv_bfloat16 g_Ah  [(size_t)NB * NN];
__device__ __nv_bfloat16 g_Al  [(size_t)NB * NN];
__device__ __nv_bfloat16 g_AhT [(size_t)NB * NN];
__device__ __nv_bfloat16 g_AlT [(size_t)NB * NN];
__device__ __nv_bfloat16 g_A2h [(size_t)NB * NN];
__device__ __nv_bfloat16 g_A2l [(size_t)NB * NN];
__device__ __nv_bfloat16 g_A2hT[(size_t)NB * NN];
__device__ __nv_bfloat16 g_A2lT[(size_t)NB * NN];
__device__ float g_D[7 * NB * N];

// ---------------- helpers ----------------
__device__ __forceinline__ uint32_t s2u(const void* p) {
    uint32_t a;
    asm("{ .reg .u64 t; cvta.to.shared.u64 t, %1; cvt.u32.u64 %0, t; }" : "=r"(a) : "l"(p));
    return a;
}

#define LDSM4(r, a)                                                           \
    asm volatile("ldmatrix.sync.aligned.m8n8.x4.shared.b16 {%0,%1,%2,%3}, [%4];" \
                 : "=r"((r)[0]), "=r"((r)[1]), "=r"((r)[2]), "=r"((r)[3]) : "r"(a))
#define LDSM2(r, a)                                                           \
    asm volatile("ldmatrix.sync.aligned.m8n8.x2.shared.b16 {%0,%1}, [%2];"    \
                 : "=r"((r)[0]), "=r"((r)[1]) : "r"(a))

__device__ __forceinline__ void mma16816(float* c, const uint32_t* a, const uint32_t* b) {
    asm volatile(
        "mma.sync.aligned.m16n8k16.row.col.f32.bf16.bf16.f32 "
        "{%0,%1,%2,%3}, {%4,%5,%6,%7}, {%8,%9}, {%0,%1,%2,%3};"
        : "+f"(c[0]), "+f"(c[1]), "+f"(c[2]), "+f"(c[3])
        : "r"(a[0]), "r"(a[1]), "r"(a[2]), "r"(a[3]), "r"(b[0]), "r"(b[1]));
}

#define CP_ASYNC(s, g) \
    asm volatile("cp.async.cg.shared.global [%0], [%1], 16;" :: "r"(s), "l"(g) : "memory")
#define CP_COMMIT() asm volatile("cp.async.commit_group;" ::: "memory")
#define CP_WAIT2()  asm volatile("cp.async.wait_group 2;" ::: "memory")
#define CP_WAIT0()  asm volatile("cp.async.wait_group 0;" ::: "memory")

// ---------------------------------------------------------------------------
// bf16-split HMMA GEMM: C[m,n] = sum_k X[m,k]*Y[k,n], fp32 out.
// Inputs: X hi/lo row-major [b][m][k]; (Y^T) hi/lo row-major [b][n][k].
// 3 products per fragment pair: hh + hl + lh into shared fp32 accumulators.
// ---------------------------------------------------------------------------
__global__ __launch_bounds__(256, 1) void gemm_bf16x3(
    const __nv_bfloat16* __restrict__ gAh, const __nv_bfloat16* __restrict__ gAl,
    const __nv_bfloat16* __restrict__ gBh, const __nv_bfloat16* __restrict__ gBl,
    float* __restrict__ C)
{
    extern __shared__ __align__(128) char smem[];
    const int tid = threadIdx.x;
    const int b  = blockIdx.z;
    const int m0 = blockIdx.y * BM;
    const int n0 = blockIdx.x * BN;
    const uint32_t sbase = s2u(smem);

    const __nv_bfloat16* gt[4] = {
        gAh + (size_t)b * NN + (size_t)m0 * N,
        gAl + (size_t)b * NN + (size_t)m0 * N,
        gBh + (size_t)b * NN + (size_t)n0 * N,
        gBl + (size_t)b * NN + (size_t)n0 * N };

    const int wid = tid >> 5, lane = tid & 31;
    const int wm = wid & 1;        // 0-1 : 64-row half
    const int wn = wid >> 1;       // 0-3 : 32-col quarter
    // ldmatrix lane address components
    const int a_row = (lane & 7) + ((lane >> 3) & 1) * 8;  // 0..15
    const int a_cb  = lane >> 4;                            // chunk bit
    const int b_row = lane & 7;
    const int b_cb  = (lane >> 3) & 1;

    float acc[4][4][4];
#pragma unroll
    for (int mi = 0; mi < 4; mi++)
#pragma unroll
        for (int ni = 0; ni < 4; ni++)
#pragma unroll
            for (int q = 0; q < 4; q++) acc[mi][ni][q] = 0.0f;

    auto load_stage = [&](int kt, int stage) {
        const int k0 = kt * BK;
        const uint32_t sb = sbase + stage * STAGEB;
#pragma unroll
        for (int t = 0; t < 4; t++) {
#pragma unroll
            for (int j = 0; j < 2; j++) {
                const int cit = tid + 256 * j;          // 0..511
                const int row = cit >> 2, ch = cit & 3;
                const __nv_bfloat16* g = gt[t] + (size_t)row * N + k0 + ch * 8;
                const uint32_t s = sb + t * TILEB + row * ROWB + ch * 16;
                CP_ASYNC(s, g);
            }
        }
        CP_COMMIT();
    };

    load_stage(0, 0);
    load_stage(1, 1);
    load_stage(2, 2);

    for (int kt = 0; kt < NT; kt++) {
        if (kt < NT - 3) CP_WAIT2(); else CP_WAIT0();
        __syncthreads();

        const uint32_t sb  = sbase + (kt % 3) * STAGEB;
        const uint32_t sAh = sb;
        const uint32_t sAl = sb + TILEB;
        const uint32_t sBh = sb + 2 * TILEB;
        const uint32_t sBl = sb + 3 * TILEB;

#pragma unroll
        for (int ks = 0; ks < 2; ks++) {
            uint32_t ah[4][4], al[4][4], bh[4][2], bl[4][2];
#pragma unroll
            for (int mi = 0; mi < 4; mi++) {
                const uint32_t ra = (uint32_t)(wm * 64 + mi * 16 + a_row) * ROWB
                                  + (uint32_t)(ks * 2 + a_cb) * 16;
                LDSM4(ah[mi], sAh + ra);
                LDSM4(al[mi], sAl + ra);
            }
#pragma unroll
            for (int ni = 0; ni < 4; ni++) {
                const uint32_t rb = (uint32_t)(wn * 32 + ni * 8 + b_row) * ROWB
                                  + (uint32_t)(ks * 2 + b_cb) * 16;
                LDSM2(bh[ni], sBh + rb);
                LDSM2(bl[ni], sBl + rb);
            }
#pragma unroll
            for (int mi = 0; mi < 4; mi++)
#pragma unroll
                for (int ni = 0; ni < 4; ni++) {
                    mma16816(acc[mi][ni], ah[mi], bh[ni]);   // hi*hi
                    mma16816(acc[mi][ni], ah[mi], bl[ni]);   // hi*lo
                    mma16816(acc[mi][ni], al[mi], bh[ni]);   // lo*hi
                }
        }
        __syncthreads();
        if (kt + 3 < NT) load_stage(kt + 3, kt % 3);
    }

    // epilogue
    float* Cb = C + (size_t)b * NN;
#pragma unroll
    for (int mi = 0; mi < 4; mi++) {
        const int rg = m0 + wm * 64 + mi * 16 + (lane >> 2);
#pragma unroll
        for (int ni = 0; ni < 4; ni++) {
            const int cg = n0 + wn * 32 + ni * 8 + (lane & 3) * 2;
            float* p = Cb + (size_t)rg * N + cg;
            *(float2*)p           = make_float2(acc[mi][ni][0], acc[mi][ni][1]);
            *(float2*)(p + 8 * N) = make_float2(acc[mi][ni][2], acc[mi][ni][3]);
        }
    }
}

// ---------------------------------------------------------------------------
// split fp32 -> bf16 hi + bf16 lo (elementwise)
// ---------------------------------------------------------------------------
__global__ __launch_bounds__(256) void split_kernel(
    const float* __restrict__ X, __nv_bfloat16* __restrict__ H,
    __nv_bfloat16* __restrict__ L)
{
    const size_t i = (size_t)blockIdx.x * blockDim.x + threadIdx.x;
    const float4 v = ((const float4*)X)[i];
    __nv_bfloat16 h0 = __float2bfloat16(v.x), h1 = __float2bfloat16(v.y),
                  h2 = __float2bfloat16(v.z), h3 = __float2bfloat16(v.w);
    __nv_bfloat16 l0 = __float2bfloat16(v.x - __bfloat162float(h0));
    __nv_bfloat16 l1 = __float2bfloat16(v.y - __bfloat162float(h1));
    __nv_bfloat16 l2 = __float2bfloat16(v.z - __bfloat162float(h2));
    __nv_bfloat16 l3 = __float2bfloat16(v.w - __bfloat162float(h3));
    ((ushort4*)H)[i] = make_ushort4(__bfloat16_as_ushort(h0), __bfloat16_as_ushort(h1),
                                    __bfloat16_as_ushort(h2), __bfloat16_as_ushort(h3));
    ((ushort4*)L)[i] = make_ushort4(__bfloat16_as_ushort(l0), __bfloat16_as_ushort(l1),
                                    __bfloat16_as_ushort(l2), __bfloat16_as_ushort(l3));
}

// ---------------------------------------------------------------------------
// fused transpose + split: HT[b][c][r] = hi(X[b][r][c]), LT likewise
// ---------------------------------------------------------------------------
__global__ __launch_bounds__(256) void splitT_kernel(
    const float* __restrict__ X, __nv_bfloat16* __restrict__ HT,
    __nv_bfloat16* __restrict__ LT)
{
    __shared__ float t[32][33];
    const int b = blockIdx.z;
    const int r0 = blockIdx.y * 32;
    const int c0 = blockIdx.x * 32;
    const int tx = threadIdx.x, ty = threadIdx.y;
    const float* Xb = X + (size_t)b * NN;
#pragma unroll
    for (int i = 0; i < 4; i++)
        t[ty + 8 * i][tx] = Xb[(size_t)(r0 + ty + 8 * i) * N + c0 + tx];
    __syncthreads();
#pragma unroll
    for (int i = 0; i < 4; i++) {
        const float v = t[tx][ty + 8 * i];
        const __nv_bfloat16 h = __float2bfloat16(v);
        const __nv_bfloat16 l = __float2bfloat16(v - __bfloat162float(h));
        const size_t o = (size_t)b * NN + (size_t)(c0 + ty + 8 * i) * N + r0 + tx;
        HT[o] = h;
        LT[o] = l;
    }
}

// ---------------------------------------------------------------------------
// diag pair-products (unchanged from R1, passing)
// ---------------------------------------------------------------------------
__global__ __launch_bounds__(256) void diag_kernel(const float* __restrict__ A)
{
    const int b = blockIdx.y;
    const int n0 = blockIdx.x * 32;
    const float* Ab  = A    + (size_t)b * NN;
    const float* A2b = g_A2 + (size_t)b * NN;
    const float* A3b = g_A3 + (size_t)b * NN;
    const float* A4b = g_A4 + (size_t)b * NN;

    __shared__ float xr[3][32][33];
    __shared__ float yc[4][32][33];
    __shared__ float red[7][8][32];

    const int tid = threadIdx.x;
    const int r = tid >> 5;
    const int c = tid & 31;

    float acc[7];
#pragma unroll
    for (int p = 0; p < 7; p++) acc[p] = 0.0f;

    for (int k0 = 0; k0 < N; k0 += 32) {
#pragma unroll
        for (int l = 0; l < 4; l++) {
            const int i = r + 8 * l;
            xr[0][i][c] = Ab [(size_t)(n0 + i) * N + k0 + c];
            xr[1][i][c] = A2b[(size_t)(n0 + i) * N + k0 + c];
            xr[2][i][c] = A4b[(size_t)(n0 + i) * N + k0 + c];
            yc[0][c][i] = Ab [(size_t)(k0 + i) * N + n0 + c];
            yc[1][c][i] = A2b[(size_t)(k0 + i) * N + n0 + c];
            yc[2][c][i] = A3b[(size_t)(k0 + i) * N + n0 + c];
            yc[3][c][i] = A4b[(size_t)(k0 + i) * N + n0 + c];
        }
        __syncthreads();

#pragma unroll
        for (int q = 0; q < 4; q++) {
            const int kk = r * 4 + q;
            const float a   = xr[0][c][kk];
            const float a2  = xr[1][c][kk];
            const float a4  = xr[2][c][kk];
            const float ca  = yc[0][c][kk];
            const float ca2 = yc[1][c][kk];
            const float ca3 = yc[2][c][kk];
            const float ca4 = yc[3][c][kk];
            acc[0] = fmaf(a,  ca,  acc[0]);
            acc[1] = fmaf(a2, ca,  acc[1]);
            acc[2] = fmaf(a2, ca2, acc[2]);
            acc[3] = fmaf(a4, ca,  acc[3]);
            acc[4] = fmaf(a4, ca2, acc[4]);
            acc[5] = fmaf(a4, ca3, acc[5]);
            acc[6] = fmaf(a4, ca4, acc[6]);
        }
        __syncthreads();
    }

#pragma unroll
    for (int p = 0; p < 7; p++) red[p][r][c] = acc[p];
    __syncthreads();

    if (r == 0) {
#pragma unroll
        for (int p = 0; p < 7; p++) {
            float s = 0.0f;
#pragma unroll
            for (int rr = 0; rr < 8; rr++) s += red[p][rr][c];
            g_D[(size_t)p * NB * N + (size_t)b * N + n0 + c] = s;
        }
    }
}

__global__ __launch_bounds__(256) void combine_kernel(
    const float* __restrict__ A, const float* __restrict__ h,
    float* __restrict__ out)
{
    const int idx = blockIdx.x * blockDim.x + threadIdx.x;
    if (idx >= NB * N * 64) return;
    const int c = idx & 63;
    const int n = (idx >> 6) & (N - 1);
    const int b = idx >> 17;

    const float d1 = A[(size_t)b * NN + (size_t)n * N + n];
    float v = h[c] + h[64 + c] * d1;
#pragma unroll
    for (int t = 2; t <= 8; t++) {
        const float dt = g_D[(size_t)(t - 2) * NB * N + (size_t)b * N + n];
        v = fmaf(h[t * 64 + c], dt, v);
    }
    out[idx] = v;
}

// ---------------------------------------------------------------------------
extern "C" void kernel_launch(void* const* d_in, const int* in_sizes, int n_in,
                              void* d_out, int out_size)
{
    const float* A = (const float*)d_in[0];   // [8, 2048, 2048]
    const float* h = (const float*)d_in[1];   // [9, 64]
    float* out = (float*)d_out;               // [8, 2048, 64]

    void *A2, *A3, *A4, *Ah, *Al, *AhT, *AlT, *A2h, *A2l, *A2hT, *A2lT;
    cudaGetSymbolAddress(&A2, g_A2);   cudaGetSymbolAddress(&A3, g_A3);
    cudaGetSymbolAddress(&A4, g_A4);
    cudaGetSymbolAddress(&Ah, g_Ah);   cudaGetSymbolAddress(&Al, g_Al);
    cudaGetSymbolAddress(&AhT, g_AhT); cudaGetSymbolAddress(&AlT, g_AlT);
    cudaGetSymbolAddress(&A2h, g_A2h); cudaGetSymbolAddress(&A2l, g_A2l);
    cudaGetSymbolAddress(&A2hT, g_A2hT); cudaGetSymbolAddress(&A2lT, g_A2lT);

    cudaFuncSetAttribute(gemm_bf16x3,
                         cudaFuncAttributeMaxDynamicSharedMemorySize, SMEM_GEMM);

    const int nvec = NB * NN / 4;
    split_kernel<<<nvec / 256, 256>>>(A, (__nv_bfloat16*)Ah, (__nv_bfloat16*)Al);
    splitT_kernel<<<dim3(N / 32, N / 32, NB), dim3(32, 8)>>>(
        A, (__nv_bfloat16*)AhT, (__nv_bfloat16*)AlT);

    const dim3 gg(N / BN, N / BM, NB);
    // A2 = A @ A
    gemm_bf16x3<<<gg, 256, SMEM_GEMM>>>(
        (const __nv_bfloat16*)Ah, (const __nv_bfloat16*)Al,
        (const __nv_bfloat16*)AhT, (const __nv_bfloat16*)AlT, (float*)A2);

    split_kernel<<<nvec / 256, 256>>>((const float*)A2, (__nv_bfloat16*)A2h,
                                      (__nv_bfloat16*)A2l);
    splitT_kernel<<<dim3(N / 32, N / 32, NB), dim3(32, 8)>>>(
        (const float*)A2, (__nv_bfloat16*)A2hT, (__nv_bfloat16*)A2lT);

    // A3 = A2 @ A
    gemm_bf16x3<<<gg, 256, SMEM_GEMM>>>(
        (const __nv_bfloat16*)A2h, (const __nv_bfloat16*)A2l,
        (const __nv_bfloat16*)AhT, (const __nv_bfloat16*)AlT, (float*)A3);
    // A4 = A2 @ A2
    gemm_bf16x3<<<gg, 256, SMEM_GEMM>>>(
        (const __nv_bfloat16*)A2h, (const __nv_bfloat16*)A2l,
        (const __nv_bfloat16*)A2hT, (const __nv_bfloat16*)A2lT, (float*)A4);

    diag_kernel<<<dim3(N / 32, NB), 256>>>(A);

    const int total = NB * N * 64;
    combine_kernel<<<(total + 255) / 256, 256>>>(A, h, out);
}

// round 4
// speedup vs baseline: 2.6326x; 1.1365x over previous
#include <cuda_runtime.h>
#include <cuda_bf16.h>
#include <cstdint>

#define N 2048
#define NB 8
#define NN (N * N)

// ---------------- GEMM tiling ----------------
#define BM 128
#define BN 128
#define BK 32
#define NT (N / BK)            // 64 k-tiles
#define ROWB 80                // padded row bytes (40 bf16, conflict-free LDSM)
#define TILEB (128 * ROWB)     // 10240 B per operand tile
#define STAGEB (4 * TILEB)     // Ah, Al, Bh, Bl = 40960 B
#define NSTAGE 4
#define SMEM_GEMM (NSTAGE * STAGEB)   // 163840 B

// ---------------- device scratch ----------------
__device__ float g_A2[(size_t)NB * NN];
__device__ float g_A3[(size_t)NB * NN];
__device__ float g_A4[(size_t)NB * NN];
__device__ __nv_bfloat16 g_Ah  [(size_t)NB * NN];
__device__ __nv_bfloat16 g_Al  [(size_t)NB * NN];
__device__ __nv_bfloat16 g_AhT [(size_t)NB * NN];
__device__ __nv_bfloat16 g_AlT [(size_t)NB * NN];
__device__ __nv_bfloat16 g_A2h [(size_t)NB * NN];
__device__ __nv_bfloat16 g_A2l [(size_t)NB * NN];
__device__ __nv_bfloat16 g_A2hT[(size_t)NB * NN];
__device__ __nv_bfloat16 g_A2lT[(size_t)NB * NN];
__device__ float g_D[7 * NB * N];

// ---------------- helpers ----------------
__device__ __forceinline__ uint32_t s2u(const void* p) {
    uint32_t a;
    asm("{ .reg .u64 t; cvta.to.shared.u64 t, %1; cvt.u32.u64 %0, t; }" : "=r"(a) : "l"(p));
    return a;
}

#define LDSM4(r, a)                                                           \
    asm volatile("ldmatrix.sync.aligned.m8n8.x4.shared.b16 {%0,%1,%2,%3}, [%4];" \
                 : "=r"((r)[0]), "=r"((r)[1]), "=r"((r)[2]), "=r"((r)[3]) : "r"(a))
#define LDSM2(r, a)                                                           \
    asm volatile("ldmatrix.sync.aligned.m8n8.x2.shared.b16 {%0,%1}, [%2];"    \
                 : "=r"((r)[0]), "=r"((r)[1]) : "r"(a))

__device__ __forceinline__ void mma16816(float* c, const uint32_t* a, const uint32_t* b) {
    asm volatile(
        "mma.sync.aligned.m16n8k16.row.col.f32.bf16.bf16.f32 "
        "{%0,%1,%2,%3}, {%4,%5,%6,%7}, {%8,%9}, {%0,%1,%2,%3};"
        : "+f"(c[0]), "+f"(c[1]), "+f"(c[2]), "+f"(c[3])
        : "r"(a[0]), "r"(a[1]), "r"(a[2]), "r"(a[3]), "r"(b[0]), "r"(b[1]));
}

#define CP_ASYNC(s, g) \
    asm volatile("cp.async.cg.shared.global [%0], [%1], 16;" :: "r"(s), "l"(g) : "memory")
#define CP_COMMIT() asm volatile("cp.async.commit_group;" ::: "memory")
#define CP_WAIT2()  asm volatile("cp.async.wait_group 2;" ::: "memory")
#define CP_WAIT1()  asm volatile("cp.async.wait_group 1;" ::: "memory")
#define CP_WAIT0()  asm volatile("cp.async.wait_group 0;" ::: "memory")

// ---------------------------------------------------------------------------
// bf16-split HMMA GEMM: C[m,n] = sum_k X[m,k]*Y[k,n], fp32 out.
// Inputs: X hi/lo row-major [b][m][k]; (Y^T) hi/lo row-major [b][n][k].
// 3 products per fragment pair (hh + hl + lh), fp32 accumulators.
// 4-stage cp.async pipeline, ONE __syncthreads per k-tile, register
// double-buffered fragments.
// ---------------------------------------------------------------------------
__global__ __launch_bounds__(256, 1) void gemm_bf16x3(
    const __nv_bfloat16* __restrict__ gAh, const __nv_bfloat16* __restrict__ gAl,
    const __nv_bfloat16* __restrict__ gBh, const __nv_bfloat16* __restrict__ gBl,
    float* __restrict__ C)
{
    extern __shared__ __align__(128) char smem[];
    const int tid = threadIdx.x;
    const int b  = blockIdx.z;
    const int m0 = blockIdx.y * BM;
    const int n0 = blockIdx.x * BN;
    const uint32_t sbase = s2u(smem);

    const __nv_bfloat16* gt[4] = {
        gAh + (size_t)b * NN + (size_t)m0 * N,
        gAl + (size_t)b * NN + (size_t)m0 * N,
        gBh + (size_t)b * NN + (size_t)n0 * N,
        gBl + (size_t)b * NN + (size_t)n0 * N };

    const int wid = tid >> 5, lane = tid & 31;
    const int wm = wid & 1;        // 0-1 : 64-row half
    const int wn = wid >> 1;       // 0-3 : 32-col quarter
    const int a_row = (lane & 7) + ((lane >> 3) & 1) * 8;  // 0..15
    const int a_cb  = lane >> 4;
    const int b_row = lane & 7;
    const int b_cb  = (lane >> 3) & 1;

    float acc[4][4][4];
#pragma unroll
    for (int mi = 0; mi < 4; mi++)
#pragma unroll
        for (int ni = 0; ni < 4; ni++)
#pragma unroll
            for (int q = 0; q < 4; q++) acc[mi][ni][q] = 0.0f;

    // cp.async addressing: 512 (row,chunk) pairs per tile, 2 per thread
    const int l_row0 = tid >> 2, l_ch0 = tid & 3;
    const int cit1 = tid + 256;
    const int l_row1 = cit1 >> 2, l_ch1 = cit1 & 3;

    auto load_stage = [&](int kt, int stage) {
        const int k0 = kt * BK;
        const uint32_t sb = sbase + stage * STAGEB;
#pragma unroll
        for (int t = 0; t < 4; t++) {
            CP_ASYNC(sb + t * TILEB + l_row0 * ROWB + l_ch0 * 16,
                     gt[t] + (size_t)l_row0 * N + k0 + l_ch0 * 8);
            CP_ASYNC(sb + t * TILEB + l_row1 * ROWB + l_ch1 * 16,
                     gt[t] + (size_t)l_row1 * N + k0 + l_ch1 * 8);
        }
        CP_COMMIT();
    };

    load_stage(0, 0);
    load_stage(1, 1);
    load_stage(2, 2);

    // per-warp LDSM base offsets (constant across k-tiles)
    const uint32_t raw = (uint32_t)(wm * 64 + a_row) * ROWB + (uint32_t)a_cb * 16;
    const uint32_t rbw = (uint32_t)(wn * 32 + b_row) * ROWB + (uint32_t)b_cb * 16;

    uint32_t ah[2][4][4], al[2][4][4], bh[2][4][2], bl[2][4][2];

    auto load_frags = [&](uint32_t sb, int ks, int pb) {
        const uint32_t sAh = sb,           sAl = sb + TILEB;
        const uint32_t sBh = sb + 2 * TILEB, sBl = sb + 3 * TILEB;
        const uint32_t ko = (uint32_t)(ks * 2) * 16;
#pragma unroll
        for (int mi = 0; mi < 4; mi++) {
            const uint32_t ra = raw + (uint32_t)(mi * 16) * ROWB + ko;
            LDSM4(ah[pb][mi], sAh + ra);
            LDSM4(al[pb][mi], sAl + ra);
        }
#pragma unroll
        for (int ni = 0; ni < 4; ni++) {
            const uint32_t rb = rbw + (uint32_t)(ni * 8) * ROWB + ko;
            LDSM2(bh[pb][ni], sBh + rb);
            LDSM2(bl[pb][ni], sBl + rb);
        }
    };

    for (int kt = 0; kt < NT; kt++) {
        if (kt < NT - 2)      CP_WAIT2();
        else if (kt == NT - 2) CP_WAIT1();
        else                  CP_WAIT0();
        __syncthreads();

        const uint32_t sb = sbase + (kt & 3) * STAGEB;

        load_frags(sb, 0, 0);                           // ks=0 fragments
        if (kt + 3 < NT) load_stage(kt + 3, (kt + 3) & 3);  // next stage (slot freed at kt-1)
        load_frags(sb, 1, 1);                           // ks=1 fragments (prefetch)

#pragma unroll
        for (int ks = 0; ks < 2; ks++) {
#pragma unroll
            for (int mi = 0; mi < 4; mi++)
#pragma unroll
                for (int ni = 0; ni < 4; ni++) {
                    mma16816(acc[mi][ni], ah[ks][mi], bh[ks][ni]);   // hi*hi
                    mma16816(acc[mi][ni], ah[ks][mi], bl[ks][ni]);   // hi*lo
                    mma16816(acc[mi][ni], al[ks][mi], bh[ks][ni]);   // lo*hi
                }
        }
    }

    // epilogue
    float* Cb = C + (size_t)b * NN;
#pragma unroll
    for (int mi = 0; mi < 4; mi++) {
        const int rg = m0 + wm * 64 + mi * 16 + (lane >> 2);
#pragma unroll
        for (int ni = 0; ni < 4; ni++) {
            const int cg = n0 + wn * 32 + ni * 8 + (lane & 3) * 2;
            float* p = Cb + (size_t)rg * N + cg;
            *(float2*)p           = make_float2(acc[mi][ni][0], acc[mi][ni][1]);
            *(float2*)(p + 8 * N) = make_float2(acc[mi][ni][2], acc[mi][ni][3]);
        }
    }
}

// ---------------------------------------------------------------------------
// split fp32 -> bf16 hi + bf16 lo (elementwise)
// ---------------------------------------------------------------------------
__global__ __launch_bounds__(256) void split_kernel(
    const float* __restrict__ X, __nv_bfloat16* __restrict__ H,
    __nv_bfloat16* __restrict__ L)
{
    const size_t i = (size_t)blockIdx.x * blockDim.x + threadIdx.x;
    const float4 v = ((const float4*)X)[i];
    __nv_bfloat16 h0 = __float2bfloat16(v.x), h1 = __float2bfloat16(v.y),
                  h2 = __float2bfloat16(v.z), h3 = __float2bfloat16(v.w);
    __nv_bfloat16 l0 = __float2bfloat16(v.x - __bfloat162float(h0));
    __nv_bfloat16 l1 = __float2bfloat16(v.y - __bfloat162float(h1));
    __nv_bfloat16 l2 = __float2bfloat16(v.z - __bfloat162float(h2));
    __nv_bfloat16 l3 = __float2bfloat16(v.w - __bfloat162float(h3));
    ((ushort4*)H)[i] = make_ushort4(__bfloat16_as_ushort(h0), __bfloat16_as_ushort(h1),
                                    __bfloat16_as_ushort(h2), __bfloat16_as_ushort(h3));
    ((ushort4*)L)[i] = make_ushort4(__bfloat16_as_ushort(l0), __bfloat16_as_ushort(l1),
                                    __bfloat16_as_ushort(l2), __bfloat16_as_ushort(l3));
}

// ---------------------------------------------------------------------------
// fused transpose + split: HT[b][c][r] = hi(X[b][r][c]), LT likewise
// ---------------------------------------------------------------------------
__global__ __launch_bounds__(256) void splitT_kernel(
    const float* __restrict__ X, __nv_bfloat16* __restrict__ HT,
    __nv_bfloat16* __restrict__ LT)
{
    __shared__ float t[32][33];
    const int b = blockIdx.z;
    const int r0 = blockIdx.y * 32;
    const int c0 = blockIdx.x * 32;
    const int tx = threadIdx.x, ty = threadIdx.y;
    const float* Xb = X + (size_t)b * NN;
#pragma unroll
    for (int i = 0; i < 4; i++)
        t[ty + 8 * i][tx] = Xb[(size_t)(r0 + ty + 8 * i) * N + c0 + tx];
    __syncthreads();
#pragma unroll
    for (int i = 0; i < 4; i++) {
        const float v = t[tx][ty + 8 * i];
        const __nv_bfloat16 h = __float2bfloat16(v);
        const __nv_bfloat16 l = __float2bfloat16(v - __bfloat162float(h));
        const size_t o = (size_t)b * NN + (size_t)(c0 + ty + 8 * i) * N + r0 + tx;
        HT[o] = h;
        LT[o] = l;
    }
}

// ---------------------------------------------------------------------------
// diag pair-products
// ---------------------------------------------------------------------------
__global__ __launch_bounds__(256) void diag_kernel(const float* __restrict__ A)
{
    const int b = blockIdx.y;
    const int n0 = blockIdx.x * 32;
    const float* Ab  = A    + (size_t)b * NN;
    const float* A2b = g_A2 + (size_t)b * NN;
    const float* A3b = g_A3 + (size_t)b * NN;
    const float* A4b = g_A4 + (size_t)b * NN;

    __shared__ float xr[3][32][33];
    __shared__ float yc[4][32][33];
    __shared__ float red[7][8][32];

    const int tid = threadIdx.x;
    const int r = tid >> 5;
    const int c = tid & 31;

    float acc[7];
#pragma unroll
    for (int p = 0; p < 7; p++) acc[p] = 0.0f;

    for (int k0 = 0; k0 < N; k0 += 32) {
#pragma unroll
        for (int l = 0; l < 4; l++) {
            const int i = r + 8 * l;
            xr[0][i][c] = Ab [(size_t)(n0 + i) * N + k0 + c];
            xr[1][i][c] = A2b[(size_t)(n0 + i) * N + k0 + c];
            xr[2][i][c] = A4b[(size_t)(n0 + i) * N + k0 + c];
            yc[0][c][i] = Ab [(size_t)(k0 + i) * N + n0 + c];
            yc[1][c][i] = A2b[(size_t)(k0 + i) * N + n0 + c];
            yc[2][c][i] = A3b[(size_t)(k0 + i) * N + n0 + c];
            yc[3][c][i] = A4b[(size_t)(k0 + i) * N + n0 + c];
        }
        __syncthreads();

#pragma unroll
        for (int q = 0; q < 4; q++) {
            const int kk = r * 4 + q;
            const float a   = xr[0][c][kk];
            const float a2  = xr[1][c][kk];
            const float a4  = xr[2][c][kk];
            const float ca  = yc[0][c][kk];
            const float ca2 = yc[1][c][kk];
            const float ca3 = yc[2][c][kk];
            const float ca4 = yc[3][c][kk];
            acc[0] = fmaf(a,  ca,  acc[0]);
            acc[1] = fmaf(a2, ca,  acc[1]);
            acc[2] = fmaf(a2, ca2, acc[2]);
            acc[3] = fmaf(a4, ca,  acc[3]);
            acc[4] = fmaf(a4, ca2, acc[4]);
            acc[5] = fmaf(a4, ca3, acc[5]);
            acc[6] = fmaf(a4, ca4, acc[6]);
        }
        __syncthreads();
    }

#pragma unroll
    for (int p = 0; p < 7; p++) red[p][r][c] = acc[p];
    __syncthreads();

    if (r == 0) {
#pragma unroll
        for (int p = 0; p < 7; p++) {
            float s = 0.0f;
#pragma unroll
            for (int rr = 0; rr < 8; rr++) s += red[p][rr][c];
            g_D[(size_t)p * NB * N + (size_t)b * N + n0 + c] = s;
        }
    }
}

__global__ __launch_bounds__(256) void combine_kernel(
    const float* __restrict__ A, const float* __restrict__ h,
    float* __restrict__ out)
{
    const int idx = blockIdx.x * blockDim.x + threadIdx.x;
    if (idx >= NB * N * 64) return;
    const int c = idx & 63;
    const int n = (idx >> 6) & (N - 1);
    const int b = idx >> 17;

    const float d1 = A[(size_t)b * NN + (size_t)n * N + n];
    float v = h[c] + h[64 + c] * d1;
#pragma unroll
    for (int t = 2; t <= 8; t++) {
        const float dt = g_D[(size_t)(t - 2) * NB * N + (size_t)b * N + n];
        v = fmaf(h[t * 64 + c], dt, v);
    }
    out[idx] = v;
}

// ---------------------------------------------------------------------------
extern "C" void kernel_launch(void* const* d_in, const int* in_sizes, int n_in,
                              void* d_out, int out_size)
{
    const float* A = (const float*)d_in[0];   // [8, 2048, 2048]
    const float* h = (const float*)d_in[1];   // [9, 64]
    float* out = (float*)d_out;               // [8, 2048, 64]

    void *A2, *A3, *A4, *Ah, *Al, *AhT, *AlT, *A2h, *A2l, *A2hT, *A2lT;
    cudaGetSymbolAddress(&A2, g_A2);   cudaGetSymbolAddress(&A3, g_A3);
    cudaGetSymbolAddress(&A4, g_A4);
    cudaGetSymbolAddress(&Ah, g_Ah);   cudaGetSymbolAddress(&Al, g_Al);
    cudaGetSymbolAddress(&AhT, g_AhT); cudaGetSymbolAddress(&AlT, g_AlT);
    cudaGetSymbolAddress(&A2h, g_A2h); cudaGetSymbolAddress(&A2l, g_A2l);
    cudaGetSymbolAddress(&A2hT, g_A2hT); cudaGetSymbolAddress(&A2lT, g_A2lT);

    cudaFuncSetAttribute(gemm_bf16x3,
                         cudaFuncAttributeMaxDynamicSharedMemorySize, SMEM_GEMM);

    const int nvec = NB * NN / 4;
    split_kernel<<<nvec / 256, 256>>>(A, (__nv_bfloat16*)Ah, (__nv_bfloat16*)Al);
    splitT_kernel<<<dim3(N / 32, N / 32, NB), dim3(32, 8)>>>(
        A, (__nv_bfloat16*)AhT, (__nv_bfloat16*)AlT);

    const dim3 gg(N / BN, N / BM, NB);
    // A2 = A @ A
    gemm_bf16x3<<<gg, 256, SMEM_GEMM>>>(
        (const __nv_bfloat16*)Ah, (const __nv_bfloat16*)Al,
        (const __nv_bfloat16*)AhT, (const __nv_bfloat16*)AlT, (float*)A2);

    split_kernel<<<nvec / 256, 256>>>((const float*)A2, (__nv_bfloat16*)A2h,
                                      (__nv_bfloat16*)A2l);
    splitT_kernel<<<dim3(N / 32, N / 32, NB), dim3(32, 8)>>>(
        (const float*)A2, (__nv_bfloat16*)A2hT, (__nv_bfloat16*)A2lT);

    // A3 = A2 @ A
    gemm_bf16x3<<<gg, 256, SMEM_GEMM>>>(
        (const __nv_bfloat16*)A2h, (const __nv_bfloat16*)A2l,
        (const __nv_bfloat16*)AhT, (const __nv_bfloat16*)AlT, (float*)A3);
    // A4 = A2 @ A2
    gemm_bf16x3<<<gg, 256, SMEM_GEMM>>>(
        (const __nv_bfloat16*)A2h, (const __nv_bfloat16*)A2l,
        (const __nv_bfloat16*)A2hT, (const __nv_bfloat16*)A2lT, (float*)A4);

    diag_kernel<<<dim3(N / 32, NB), 256>>>(A);

    const int total = NB * N * 64;
    combine_kernel<<<(total + 255) / 256, 256>>>(A, h, out);
}

// round 5
// speedup vs baseline: 2.8101x; 1.0674x over previous
#include <cuda_runtime.h>
#include <cuda_bf16.h>
#include <cstdint>

#define N 2048
#define NB 8
#define NN (N * N)

// ---------------- GEMM tiling ----------------
#define BM 128
#define BN 256
#define BK 32
#define NT (N / BK)              // 64 k-tiles
#define ROWB 80                  // padded row bytes (conflict-free LDSM)
#define TILEA (128 * ROWB)       // 10240 B
#define TILEB (256 * ROWB)       // 20480 B
#define STAGEB (2 * TILEA + 2 * TILEB)   // 61440 B
#define NSTAGE 3
#define SMEM_GEMM (NSTAGE * STAGEB)      // 184320 B

// ---------------- device scratch ----------------
__device__ float g_A2[(size_t)NB * NN];
__device__ float g_A3[(size_t)NB * NN];
__device__ float g_A4[(size_t)NB * NN];
__device__ __nv_bfloat16 g_Ah  [(size_t)NB * NN];
__device__ __nv_bfloat16 g_Al  [(size_t)NB * NN];
__device__ __nv_bfloat16 g_AhT [(size_t)NB * NN];
__device__ __nv_bfloat16 g_AlT [(size_t)NB * NN];
__device__ __nv_bfloat16 g_A2h [(size_t)NB * NN];
__device__ __nv_bfloat16 g_A2l [(size_t)NB * NN];
__device__ __nv_bfloat16 g_A2hT[(size_t)NB * NN];
__device__ __nv_bfloat16 g_A2lT[(size_t)NB * NN];
__device__ float g_D[7 * NB * N];

// ---------------- helpers ----------------
__device__ __forceinline__ uint32_t s2u(const void* p) {
    uint32_t a;
    asm("{ .reg .u64 t; cvta.to.shared.u64 t, %1; cvt.u32.u64 %0, t; }" : "=r"(a) : "l"(p));
    return a;
}

#define LDSM4(r0, r1, r2, r3, a)                                              \
    asm volatile("ldmatrix.sync.aligned.m8n8.x4.shared.b16 {%0,%1,%2,%3}, [%4];" \
                 : "=r"(r0), "=r"(r1), "=r"(r2), "=r"(r3) : "r"(a))

__device__ __forceinline__ void mma16816(float* c, const uint32_t* a, const uint32_t* b) {
    asm volatile(
        "mma.sync.aligned.m16n8k16.row.col.f32.bf16.bf16.f32 "
        "{%0,%1,%2,%3}, {%4,%5,%6,%7}, {%8,%9}, {%0,%1,%2,%3};"
        : "+f"(c[0]), "+f"(c[1]), "+f"(c[2]), "+f"(c[3])
        : "r"(a[0]), "r"(a[1]), "r"(a[2]), "r"(a[3]), "r"(b[0]), "r"(b[1]));
}

#define CP_ASYNC(s, g) \
    asm volatile("cp.async.cg.shared.global [%0], [%1], 16;" :: "r"(s), "l"(g) : "memory")
#define CP_COMMIT() asm volatile("cp.async.commit_group;" ::: "memory")
#define CP_WAIT1()  asm volatile("cp.async.wait_group 1;" ::: "memory")
#define CP_WAIT0()  asm volatile("cp.async.wait_group 0;" ::: "memory")

// ---------------------------------------------------------------------------
// bf16-split HMMA GEMM: C[m,n] = sum_k X[m,k]*Y[k,n], fp32 out.
// 128x256 block tile, 8 warps, 64x64 warp tile, 3-stage cp.async pipeline.
// Per fragment pair: hh + hl + lh (fp32 accum).
// ---------------------------------------------------------------------------
__global__ __launch_bounds__(256, 1) void gemm_bf16x3(
    const __nv_bfloat16* __restrict__ gAh, const __nv_bfloat16* __restrict__ gAl,
    const __nv_bfloat16* __restrict__ gBh, const __nv_bfloat16* __restrict__ gBl,
    float* __restrict__ C)
{
    extern __shared__ __align__(128) char smem[];
    const int tid = threadIdx.x;
    const int b  = blockIdx.z;
    const int m0 = blockIdx.y * BM;
    const int n0 = blockIdx.x * BN;
    const uint32_t sbase = s2u(smem);

    const __nv_bfloat16* gA0 = gAh + (size_t)b * NN + (size_t)m0 * N;
    const __nv_bfloat16* gA1 = gAl + (size_t)b * NN + (size_t)m0 * N;
    const __nv_bfloat16* gB0 = gBh + (size_t)b * NN + (size_t)n0 * N;
    const __nv_bfloat16* gB1 = gBl + (size_t)b * NN + (size_t)n0 * N;

    const int wid = tid >> 5, lane = tid & 31;
    const int wm = wid & 1;        // 0-1 : 64-row half
    const int wn = wid >> 1;       // 0-3 : 64-col quarter
    // A ldmatrix lane mapping (x4: m16 x k16)
    const int a_row = lane & 15;
    const int a_cb  = lane >> 4;          // k-chunk bit
    // B ldmatrix lane mapping (x4: n16 x k16 -> 2 ni * 2 kchunks)
    const int b_row = ((lane >> 4) << 3) + (lane & 7);  // n-row within 16-block
    const int b_cb  = (lane >> 3) & 1;                  // k-chunk bit

    float acc[4][8][4];
#pragma unroll
    for (int mi = 0; mi < 4; mi++)
#pragma unroll
        for (int ni = 0; ni < 8; ni++)
#pragma unroll
            for (int q = 0; q < 4; q++) acc[mi][ni][q] = 0.0f;

    auto load_stage = [&](int kt, int stage) {
        const int k0 = kt * BK;
        const uint32_t sb = sbase + stage * STAGEB;
        // A tiles: 512 16B-chunks each, 2 per thread
#pragma unroll
        for (int j = 0; j < 2; j++) {
            const int cit = tid + 256 * j;
            const int row = cit >> 2, ch = cit & 3;
            const uint32_t so = (uint32_t)row * ROWB + ch * 16;
            CP_ASYNC(sb + so,         gA0 + (size_t)row * N + k0 + ch * 8);
            CP_ASYNC(sb + TILEA + so, gA1 + (size_t)row * N + k0 + ch * 8);
        }
        // B tiles: 1024 16B-chunks each, 4 per thread
#pragma unroll
        for (int j = 0; j < 4; j++) {
            const int cit = tid + 256 * j;
            const int row = cit >> 2, ch = cit & 3;
            const uint32_t so = (uint32_t)row * ROWB + ch * 16;
            CP_ASYNC(sb + 2 * TILEA + so,         gB0 + (size_t)row * N + k0 + ch * 8);
            CP_ASYNC(sb + 2 * TILEA + TILEB + so, gB1 + (size_t)row * N + k0 + ch * 8);
        }
        CP_COMMIT();
    };

    load_stage(0, 0);
    load_stage(1, 1);

    const uint32_t raw = (uint32_t)(wm * 64 + a_row) * ROWB + (uint32_t)a_cb * 16;
    const uint32_t rbw = (uint32_t)(wn * 64 + b_row) * ROWB + (uint32_t)b_cb * 16;

    uint32_t ah[4][4], al[4][4], bh[8][2], bl[8][2];

    auto load_frags = [&](uint32_t sb, int ks) {
        const uint32_t sAh = sb, sAl = sb + TILEA;
        const uint32_t sBh = sb + 2 * TILEA, sBl = sb + 2 * TILEA + TILEB;
        const uint32_t ko = (uint32_t)ks * 32;
#pragma unroll
        for (int mi = 0; mi < 4; mi++) {
            const uint32_t ra = raw + (uint32_t)(mi * 16) * ROWB + ko;
            LDSM4(ah[mi][0], ah[mi][1], ah[mi][2], ah[mi][3], sAh + ra);
            LDSM4(al[mi][0], al[mi][1], al[mi][2], al[mi][3], sAl + ra);
        }
#pragma unroll
        for (int nj = 0; nj < 4; nj++) {
            const uint32_t rb = rbw + (uint32_t)(nj * 16) * ROWB + ko;
            LDSM4(bh[2 * nj][0], bh[2 * nj][1], bh[2 * nj + 1][0], bh[2 * nj + 1][1],
                  sBh + rb);
            LDSM4(bl[2 * nj][0], bl[2 * nj][1], bl[2 * nj + 1][0], bl[2 * nj + 1][1],
                  sBl + rb);
        }
    };

    auto do_mmas = [&]() {
#pragma unroll
        for (int mi = 0; mi < 4; mi++)
#pragma unroll
            for (int ni = 0; ni < 8; ni++) {
                mma16816(acc[mi][ni], ah[mi], bh[ni]);   // hi*hi
                mma16816(acc[mi][ni], ah[mi], bl[ni]);   // hi*lo
                mma16816(acc[mi][ni], al[mi], bh[ni]);   // lo*hi
            }
    };

    for (int kt = 0; kt < NT; kt++) {
        if (kt < NT - 1) CP_WAIT1(); else CP_WAIT0();
        __syncthreads();
        const uint32_t sb = sbase + (kt % 3) * STAGEB;

        load_frags(sb, 0);
        if (kt + 2 < NT) load_stage(kt + 2, (kt + 2) % 3);
        do_mmas();
        load_frags(sb, 1);
        do_mmas();
    }

    // epilogue
    float* Cb = C + (size_t)b * NN;
#pragma unroll
    for (int mi = 0; mi < 4; mi++) {
        const int rg = m0 + wm * 64 + mi * 16 + (lane >> 2);
#pragma unroll
        for (int ni = 0; ni < 8; ni++) {
            const int cg = n0 + wn * 64 + ni * 8 + (lane & 3) * 2;
            float* p = Cb + (size_t)rg * N + cg;
            *(float2*)p           = make_float2(acc[mi][ni][0], acc[mi][ni][1]);
            *(float2*)(p + 8 * N) = make_float2(acc[mi][ni][2], acc[mi][ni][3]);
        }
    }
}

// ---------------------------------------------------------------------------
// fused split + transpose-split: from X produce H,L (row-major) and HT,LT
// (transposed), reading X exactly once.
// ---------------------------------------------------------------------------
__global__ __launch_bounds__(256) void split_both_kernel(
    const float* __restrict__ X,
    __nv_bfloat16* __restrict__ H,  __nv_bfloat16* __restrict__ L,
    __nv_bfloat16* __restrict__ HT, __nv_bfloat16* __restrict__ LT)
{
    __shared__ float t[32][33];
    const int b = blockIdx.z;
    const int r0 = blockIdx.y * 32;
    const int c0 = blockIdx.x * 32;
    const int tx = threadIdx.x, ty = threadIdx.y;
    const float* Xb = X + (size_t)b * NN;
#pragma unroll
    for (int i = 0; i < 4; i++) {
        const float v = Xb[(size_t)(r0 + ty + 8 * i) * N + c0 + tx];
        t[ty + 8 * i][tx] = v;
        const __nv_bfloat16 h = __float2bfloat16(v);
        const __nv_bfloat16 l = __float2bfloat16(v - __bfloat162float(h));
        const size_t o = (size_t)b * NN + (size_t)(r0 + ty + 8 * i) * N + c0 + tx;
        H[o] = h;
        L[o] = l;
    }
    __syncthreads();
#pragma unroll
    for (int i = 0; i < 4; i++) {
        const float v = t[tx][ty + 8 * i];
        const __nv_bfloat16 h = __float2bfloat16(v);
        const __nv_bfloat16 l = __float2bfloat16(v - __bfloat162float(h));
        const size_t o = (size_t)b * NN + (size_t)(c0 + ty + 8 * i) * N + r0 + tx;
        HT[o] = h;
        LT[o] = l;
    }
}

// ---------------------------------------------------------------------------
// diag pair-products
// ---------------------------------------------------------------------------
__global__ __launch_bounds__(256) void diag_kernel(const float* __restrict__ A)
{
    const int b = blockIdx.y;
    const int n0 = blockIdx.x * 32;
    const float* Ab  = A    + (size_t)b * NN;
    const float* A2b = g_A2 + (size_t)b * NN;
    const float* A3b = g_A3 + (size_t)b * NN;
    const float* A4b = g_A4 + (size_t)b * NN;

    __shared__ float xr[3][32][33];
    __shared__ float yc[4][32][33];
    __shared__ float red[7][8][32];

    const int tid = threadIdx.x;
    const int r = tid >> 5;
    const int c = tid & 31;

    float acc[7];
#pragma unroll
    for (int p = 0; p < 7; p++) acc[p] = 0.0f;

    for (int k0 = 0; k0 < N; k0 += 32) {
#pragma unroll
        for (int l = 0; l < 4; l++) {
            const int i = r + 8 * l;
            xr[0][i][c] = Ab [(size_t)(n0 + i) * N + k0 + c];
            xr[1][i][c] = A2b[(size_t)(n0 + i) * N + k0 + c];
            xr[2][i][c] = A4b[(size_t)(n0 + i) * N + k0 + c];
            yc[0][c][i] = Ab [(size_t)(k0 + i) * N + n0 + c];
            yc[1][c][i] = A2b[(size_t)(k0 + i) * N + n0 + c];
            yc[2][c][i] = A3b[(size_t)(k0 + i) * N + n0 + c];
            yc[3][c][i] = A4b[(size_t)(k0 + i) * N + n0 + c];
        }
        __syncthreads();

#pragma unroll
        for (int q = 0; q < 4; q++) {
            const int kk = r * 4 + q;
            const float a   = xr[0][c][kk];
            const float a2  = xr[1][c][kk];
            const float a4  = xr[2][c][kk];
            const float ca  = yc[0][c][kk];
            const float ca2 = yc[1][c][kk];
            const float ca3 = yc[2][c][kk];
            const float ca4 = yc[3][c][kk];
            acc[0] = fmaf(a,  ca,  acc[0]);
            acc[1] = fmaf(a2, ca,  acc[1]);
            acc[2] = fmaf(a2, ca2, acc[2]);
            acc[3] = fmaf(a4, ca,  acc[3]);
            acc[4] = fmaf(a4, ca2, acc[4]);
            acc[5] = fmaf(a4, ca3, acc[5]);
            acc[6] = fmaf(a4, ca4, acc[6]);
        }
        __syncthreads();
    }

#pragma unroll
    for (int p = 0; p < 7; p++) red[p][r][c] = acc[p];
    __syncthreads();

    if (r == 0) {
#pragma unroll
        for (int p = 0; p < 7; p++) {
            float s = 0.0f;
#pragma unroll
            for (int rr = 0; rr < 8; rr++) s += red[p][rr][c];
            g_D[(size_t)p * NB * N + (size_t)b * N + n0 + c] = s;
        }
    }
}

__global__ __launch_bounds__(256) void combine_kernel(
    const float* __restrict__ A, const float* __restrict__ h,
    float* __restrict__ out)
{
    const int idx = blockIdx.x * blockDim.x + threadIdx.x;
    if (idx >= NB * N * 64) return;
    const int c = idx & 63;
    const int n = (idx >> 6) & (N - 1);
    const int b = idx >> 17;

    const float d1 = A[(size_t)b * NN + (size_t)n * N + n];
    float v = h[c] + h[64 + c] * d1;
#pragma unroll
    for (int t = 2; t <= 8; t++) {
        const float dt = g_D[(size_t)(t - 2) * NB * N + (size_t)b * N + n];
        v = fmaf(h[t * 64 + c], dt, v);
    }
    out[idx] = v;
}

// ---------------------------------------------------------------------------
extern "C" void kernel_launch(void* const* d_in, const int* in_sizes, int n_in,
                              void* d_out, int out_size)
{
    const float* A = (const float*)d_in[0];   // [8, 2048, 2048]
    const float* h = (const float*)d_in[1];   // [9, 64]
    float* out = (float*)d_out;               // [8, 2048, 64]

    void *A2, *A3, *A4, *Ah, *Al, *AhT, *AlT, *A2h, *A2l, *A2hT, *A2lT;
    cudaGetSymbolAddress(&A2, g_A2);   cudaGetSymbolAddress(&A3, g_A3);
    cudaGetSymbolAddress(&A4, g_A4);
    cudaGetSymbolAddress(&Ah, g_Ah);   cudaGetSymbolAddress(&Al, g_Al);
    cudaGetSymbolAddress(&AhT, g_AhT); cudaGetSymbolAddress(&AlT, g_AlT);
    cudaGetSymbolAddress(&A2h, g_A2h); cudaGetSymbolAddress(&A2l, g_A2l);
    cudaGetSymbolAddress(&A2hT, g_A2hT); cudaGetSymbolAddress(&A2lT, g_A2lT);

    cudaFuncSetAttribute(gemm_bf16x3,
                         cudaFuncAttributeMaxDynamicSharedMemorySize, SMEM_GEMM);

    split_both_kernel<<<dim3(N / 32, N / 32, NB), dim3(32, 8)>>>(
        A, (__nv_bfloat16*)Ah, (__nv_bfloat16*)Al,
        (__nv_bfloat16*)AhT, (__nv_bfloat16*)AlT);

    const dim3 gg(N / BN, N / BM, NB);
    // A2 = A @ A
    gemm_bf16x3<<<gg, 256, SMEM_GEMM>>>(
        (const __nv_bfloat16*)Ah, (const __nv_bfloat16*)Al,
        (const __nv_bfloat16*)AhT, (const __nv_bfloat16*)AlT, (float*)A2);

    split_both_kernel<<<dim3(N / 32, N / 32, NB), dim3(32, 8)>>>(
        (const float*)A2, (__nv_bfloat16*)A2h, (__nv_bfloat16*)A2l,
        (__nv_bfloat16*)A2hT, (__nv_bfloat16*)A2lT);

    // A3 = A2 @ A
    gemm_bf16x3<<<gg, 256, SMEM_GEMM>>>(
        (const __nv_bfloat16*)A2h, (const __nv_bfloat16*)A2l,
        (const __nv_bfloat16*)AhT, (const __nv_bfloat16*)AlT, (float*)A3);
    // A4 = A2 @ A2
    gemm_bf16x3<<<gg, 256, SMEM_GEMM>>>(
        (const __nv_bfloat16*)A2h, (const __nv_bfloat16*)A2l,
        (const __nv_bfloat16*)A2hT, (const __nv_bfloat16*)A2lT, (float*)A4);

    diag_kernel<<<dim3(N / 32, NB), 256>>>(A);

    const int total = NB * N * 64;
    combine_kernel<<<(total + 255) / 256, 256>>>(A, h, out);
}

// round 6
// speedup vs baseline: 3.6393x; 1.2950x over previous
#include <cuda_runtime.h>
#include <cuda_bf16.h>
#include <cuda.h>
#include <cstdint>

#define N 2048
#define NB 8
#define NN (N * N)

// ---------------- GEMM tiling ----------------
#define BM 128
#define BN 256
#define BK 64                     // 64 bf16 = 128 B rows (SW128)
#define NT (N / BK)               // 32 k-tiles
#define OFF_AL 16384              // A tile = 128 rows * 128 B
#define OFF_BH 32768
#define OFF_BL 65536              // B tile = 256 rows * 128 B
#define STAGEB 98304
#define SMEM_GEMM (2 * STAGEB)    // 196608 B, 2-stage ping-pong

// ---------------- device scratch ----------------
__device__ float g_A2[(size_t)NB * NN];
__device__ float g_A3[(size_t)NB * NN];
__device__ float g_A4[(size_t)NB * NN];
__device__ __nv_bfloat16 g_Ah  [(size_t)NB * NN];
__device__ __nv_bfloat16 g_Al  [(size_t)NB * NN];
__device__ __nv_bfloat16 g_AhT [(size_t)NB * NN];
__device__ __nv_bfloat16 g_AlT [(size_t)NB * NN];
__device__ __nv_bfloat16 g_A2h [(size_t)NB * NN];
__device__ __nv_bfloat16 g_A2l [(size_t)NB * NN];
__device__ __nv_bfloat16 g_A2hT[(size_t)NB * NN];
__device__ __nv_bfloat16 g_A2lT[(size_t)NB * NN];
__device__ float g_D[7 * NB * N];

// ---------------- helpers ----------------
__device__ __forceinline__ uint32_t s2u(const void* p) {
    uint32_t a;
    asm("{ .reg .u64 t; cvta.to.shared.u64 t, %1; cvt.u32.u64 %0, t; }" : "=r"(a) : "l"(p));
    return a;
}

#define LDSM4(r0, r1, r2, r3, a)                                              \
    asm volatile("ldmatrix.sync.aligned.m8n8.x4.shared.b16 {%0,%1,%2,%3}, [%4];" \
                 : "=r"(r0), "=r"(r1), "=r"(r2), "=r"(r3) : "r"(a))

__device__ __forceinline__ void mma16816(float* c, const uint32_t* a, const uint32_t* b) {
    asm volatile(
        "mma.sync.aligned.m16n8k16.row.col.f32.bf16.bf16.f32 "
        "{%0,%1,%2,%3}, {%4,%5,%6,%7}, {%8,%9}, {%0,%1,%2,%3};"
        : "+f"(c[0]), "+f"(c[1]), "+f"(c[2]), "+f"(c[3])
        : "r"(a[0]), "r"(a[1]), "r"(a[2]), "r"(a[3]), "r"(b[0]), "r"(b[1]));
}

#define MBARRIER_INIT(addr, cnt) \
    asm volatile("mbarrier.init.shared.b64 [%0], %1;" :: "r"(addr), "r"((uint32_t)(cnt)) : "memory")
#define MBARRIER_EXPECT_TX(addr, bytes) \
    asm volatile("mbarrier.arrive.expect_tx.shared.b64 _, [%0], %1;" \
                 :: "r"(addr), "r"((uint32_t)(bytes)) : "memory")
#define MBAR_WAIT(addr, ph) do {                                              \
    asm volatile(                                                             \
        "{\n\t.reg .pred P1;\n\t"                                             \
        "WL_%=:\n\t"                                                          \
        "mbarrier.try_wait.parity.acquire.cta.shared::cta.b64 P1, [%0], %1, 0x989680;\n\t" \
        "@P1 bra.uni WD_%=;\n\t"                                              \
        "bra.uni WL_%=;\n\t"                                                  \
        "WD_%=:\n\t}"                                                         \
        :: "r"(addr), "r"((uint32_t)(ph)) : "memory");                        \
} while (0)

#define TMA_LOAD_3D(smem_addr, tmap, cx, cy, cz, mbar)                        \
    asm volatile(                                                             \
        "cp.async.bulk.tensor.3d.shared::cta.global.tile.mbarrier::complete_tx::bytes " \
        "[%0], [%1, {%2, %3, %4}], [%5];"                                     \
        :: "r"((uint32_t)(smem_addr)), "l"(tmap), "r"((int32_t)(cx)),         \
           "r"((int32_t)(cy)), "r"((int32_t)(cz)), "r"((uint32_t)(mbar))      \
        : "memory")

// ---------------------------------------------------------------------------
// bf16-split HMMA GEMM with TMA double-buffering.
// C[m,n] = sum_k X[m,k]*Y[k,n]; A maps = X hi/lo row-major; B maps = Y^T hi/lo.
// 128x256 block, 8 warps (2x4), 64x64 warp tile, hh+hl+lh products.
// ---------------------------------------------------------------------------
__global__ __launch_bounds__(256, 1) void gemm_tma(
    const __grid_constant__ CUtensorMap tAh,
    const __grid_constant__ CUtensorMap tAl,
    const __grid_constant__ CUtensorMap tBh,
    const __grid_constant__ CUtensorMap tBl,
    float* __restrict__ C)
{
    extern __shared__ __align__(1024) char smem[];
    __shared__ __align__(8) uint64_t mbar[2];

    const int tid = threadIdx.x;
    const int b  = blockIdx.z;
    const int m0 = blockIdx.y * BM;
    const int n0 = blockIdx.x * BN;
    const uint32_t sbase = s2u(smem);
    const uint32_t barb  = s2u(mbar);

    const int wid = tid >> 5, lane = tid & 31;
    const int wm = wid & 1;
    const int wn = wid >> 1;
    const int a_row = lane & 15;
    const int a_cb  = lane >> 4;
    const int b_row = ((lane >> 4) << 3) + (lane & 7);
    const int b_cb  = (lane >> 3) & 1;
    const uint32_t rx7 = (uint32_t)(lane & 7);

    if (tid == 0) {
        MBARRIER_INIT(barb, 1);
        MBARRIER_INIT(barb + 8, 1);
    }
    __syncthreads();

    auto issue_stage = [&](int kt, int buf) {
        const uint32_t fullb = barb + 8 * buf;
        const uint32_t sb = sbase + buf * STAGEB;
        const int k0 = kt * BK;
        MBARRIER_EXPECT_TX(fullb, STAGEB);
        TMA_LOAD_3D(sb,           &tAh, k0, m0, b, fullb);
        TMA_LOAD_3D(sb + OFF_AL,  &tAl, k0, m0, b, fullb);
        TMA_LOAD_3D(sb + OFF_BH,  &tBh, k0, n0, b, fullb);
        TMA_LOAD_3D(sb + OFF_BL,  &tBl, k0, n0, b, fullb);
    };

    if (tid == 0) {
        issue_stage(0, 0);
        issue_stage(1, 1);
    }

    float acc[4][8][4];
#pragma unroll
    for (int mi = 0; mi < 4; mi++)
#pragma unroll
        for (int ni = 0; ni < 8; ni++)
#pragma unroll
            for (int q = 0; q < 4; q++) acc[mi][ni][q] = 0.0f;

    uint32_t ah[4][4], al[4][4], bh[8][2], bl[8][2];

    const uint32_t rowA = (uint32_t)(wm * 64 + a_row) * 128;
    const uint32_t rowB = (uint32_t)(wn * 64 + b_row) * 128;

    for (int kt = 0; kt < NT; kt++) {
        const int buf = kt & 1;
        MBAR_WAIT(barb + 8 * buf, (kt >> 1) & 1);
        const uint32_t sb = sbase + buf * STAGEB;

#pragma unroll
        for (int ks = 0; ks < 4; ks++) {
            // SW128 swizzle: byteoff = row*128 + ((chunk ^ (row&7))*16)
            const uint32_t cxa = (uint32_t)((ks * 2 + a_cb) ^ rx7) * 16;
            const uint32_t cxb = (uint32_t)((ks * 2 + b_cb) ^ rx7) * 16;
#pragma unroll
            for (int mi = 0; mi < 4; mi++) {
                const uint32_t ra = sb + rowA + (uint32_t)(mi * 16) * 128 + cxa;
                LDSM4(ah[mi][0], ah[mi][1], ah[mi][2], ah[mi][3], ra);
                LDSM4(al[mi][0], al[mi][1], al[mi][2], al[mi][3], ra + OFF_AL);
            }
#pragma unroll
            for (int nj = 0; nj < 4; nj++) {
                const uint32_t rb = sb + OFF_BH + rowB + (uint32_t)(nj * 16) * 128 + cxb;
                LDSM4(bh[2 * nj][0], bh[2 * nj][1], bh[2 * nj + 1][0], bh[2 * nj + 1][1], rb);
                LDSM4(bl[2 * nj][0], bl[2 * nj][1], bl[2 * nj + 1][0], bl[2 * nj + 1][1],
                      rb + (OFF_BL - OFF_BH));
            }
#pragma unroll
            for (int mi = 0; mi < 4; mi++)
#pragma unroll
                for (int ni = 0; ni < 8; ni++) {
                    mma16816(acc[mi][ni], ah[mi], bh[ni]);   // hi*hi
                    mma16816(acc[mi][ni], ah[mi], bl[ni]);   // hi*lo
                    mma16816(acc[mi][ni], al[mi], bh[ni]);   // lo*hi
                }
        }
        __syncthreads();
        if (tid == 0 && kt + 2 < NT) issue_stage(kt + 2, buf);
    }

    // epilogue
    float* Cb = C + (size_t)b * NN;
#pragma unroll
    for (int mi = 0; mi < 4; mi++) {
        const int rg = m0 + wm * 64 + mi * 16 + (lane >> 2);
#pragma unroll
        for (int ni = 0; ni < 8; ni++) {
            const int cg = n0 + wn * 64 + ni * 8 + (lane & 3) * 2;
            float* p = Cb + (size_t)rg * N + cg;
            *(float2*)p           = make_float2(acc[mi][ni][0], acc[mi][ni][1]);
            *(float2*)(p + 8 * N) = make_float2(acc[mi][ni][2], acc[mi][ni][3]);
        }
    }
}

// ---------------------------------------------------------------------------
// fused split + transpose-split: H,L row-major; HT,LT transposed; one X read.
// ---------------------------------------------------------------------------
__global__ __launch_bounds__(256) void split_both_kernel(
    const float* __restrict__ X,
    __nv_bfloat16* __restrict__ H,  __nv_bfloat16* __restrict__ L,
    __nv_bfloat16* __restrict__ HT, __nv_bfloat16* __restrict__ LT)
{
    __shared__ float t[32][33];
    const int b = blockIdx.z;
    const int r0 = blockIdx.y * 32;
    const int c0 = blockIdx.x * 32;
    const int tx = threadIdx.x, ty = threadIdx.y;
    const float* Xb = X + (size_t)b * NN;
#pragma unroll
    for (int i = 0; i < 4; i++) {
        const float v = Xb[(size_t)(r0 + ty + 8 * i) * N + c0 + tx];
        t[ty + 8 * i][tx] = v;
        const __nv_bfloat16 h = __float2bfloat16(v);
        const __nv_bfloat16 l = __float2bfloat16(v - __bfloat162float(h));
        const size_t o = (size_t)b * NN + (size_t)(r0 + ty + 8 * i) * N + c0 + tx;
        H[o] = h;
        L[o] = l;
    }
    __syncthreads();
#pragma unroll
    for (int i = 0; i < 4; i++) {
        const float v = t[tx][ty + 8 * i];
        const __nv_bfloat16 h = __float2bfloat16(v);
        const __nv_bfloat16 l = __float2bfloat16(v - __bfloat162float(h));
        const size_t o = (size_t)b * NN + (size_t)(c0 + ty + 8 * i) * N + r0 + tx;
        HT[o] = h;
        LT[o] = l;
    }
}

// ---------------------------------------------------------------------------
// diag pair-products
// ---------------------------------------------------------------------------
__global__ __launch_bounds__(256) void diag_kernel(const float* __restrict__ A)
{
    const int b = blockIdx.y;
    const int n0 = blockIdx.x * 32;
    const float* Ab  = A    + (size_t)b * NN;
    const float* A2b = g_A2 + (size_t)b * NN;
    const float* A3b = g_A3 + (size_t)b * NN;
    const float* A4b = g_A4 + (size_t)b * NN;

    __shared__ float xr[3][32][33];
    __shared__ float yc[4][32][33];
    __shared__ float red[7][8][32];

    const int tid = threadIdx.x;
    const int r = tid >> 5;
    const int c = tid & 31;

    float acc[7];
#pragma unroll
    for (int p = 0; p < 7; p++) acc[p] = 0.0f;

    for (int k0 = 0; k0 < N; k0 += 32) {
#pragma unroll
        for (int l = 0; l < 4; l++) {
            const int i = r + 8 * l;
            xr[0][i][c] = Ab [(size_t)(n0 + i) * N + k0 + c];
            xr[1][i][c] = A2b[(size_t)(n0 + i) * N + k0 + c];
            xr[2][i][c] = A4b[(size_t)(n0 + i) * N + k0 + c];
            yc[0][c][i] = Ab [(size_t)(k0 + i) * N + n0 + c];
            yc[1][c][i] = A2b[(size_t)(k0 + i) * N + n0 + c];
            yc[2][c][i] = A3b[(size_t)(k0 + i) * N + n0 + c];
            yc[3][c][i] = A4b[(size_t)(k0 + i) * N + n0 + c];
        }
        __syncthreads();

#pragma unroll
        for (int q = 0; q < 4; q++) {
            const int kk = r * 4 + q;
            const float a   = xr[0][c][kk];
            const float a2  = xr[1][c][kk];
            const float a4  = xr[2][c][kk];
            const float ca  = yc[0][c][kk];
            const float ca2 = yc[1][c][kk];
            const float ca3 = yc[2][c][kk];
            const float ca4 = yc[3][c][kk];
            acc[0] = fmaf(a,  ca,  acc[0]);
            acc[1] = fmaf(a2, ca,  acc[1]);
            acc[2] = fmaf(a2, ca2, acc[2]);
            acc[3] = fmaf(a4, ca,  acc[3]);
            acc[4] = fmaf(a4, ca2, acc[4]);
            acc[5] = fmaf(a4, ca3, acc[5]);
            acc[6] = fmaf(a4, ca4, acc[6]);
        }
        __syncthreads();
    }

#pragma unroll
    for (int p = 0; p < 7; p++) red[p][r][c] = acc[p];
    __syncthreads();

    if (r == 0) {
#pragma unroll
        for (int p = 0; p < 7; p++) {
            float s = 0.0f;
#pragma unroll
            for (int rr = 0; rr < 8; rr++) s += red[p][rr][c];
            g_D[(size_t)p * NB * N + (size_t)b * N + n0 + c] = s;
        }
    }
}

__global__ __launch_bounds__(256) void combine_kernel(
    const float* __restrict__ A, const float* __restrict__ h,
    float* __restrict__ out)
{
    const int idx = blockIdx.x * blockDim.x + threadIdx.x;
    if (idx >= NB * N * 64) return;
    const int c = idx & 63;
    const int n = (idx >> 6) & (N - 1);
    const int b = idx >> 17;

    const float d1 = A[(size_t)b * NN + (size_t)n * N + n];
    float v = h[c] + h[64 + c] * d1;
#pragma unroll
    for (int t = 2; t <= 8; t++) {
        const float dt = g_D[(size_t)(t - 2) * NB * N + (size_t)b * N + n];
        v = fmaf(h[t * 64 + c], dt, v);
    }
    out[idx] = v;
}

// ---------------------------------------------------------------------------
// host
// ---------------------------------------------------------------------------
typedef CUresult (*PFN_tmap_encode)(
    CUtensorMap*, CUtensorMapDataType, cuuint32_t, void*,
    const cuuint64_t*, const cuuint64_t*, const cuuint32_t*, const cuuint32_t*,
    CUtensorMapInterleave, CUtensorMapSwizzle, CUtensorMapL2promotion,
    CUtensorMapFloatOOBfill);

static CUtensorMap make_map(PFN_tmap_encode enc, void* ptr, uint32_t box_rows) {
    CUtensorMap m{};
    cuuint64_t dims[3]    = {N, N, NB};
    cuuint64_t strides[2] = {(cuuint64_t)N * 2, (cuuint64_t)NN * 2};
    cuuint32_t box[3]     = {BK, box_rows, 1};
    cuuint32_t es[3]      = {1, 1, 1};
    enc(&m, CU_TENSOR_MAP_DATA_TYPE_BFLOAT16, 3, ptr, dims, strides, box, es,
        CU_TENSOR_MAP_INTERLEAVE_NONE, CU_TENSOR_MAP_SWIZZLE_128B,
        CU_TENSOR_MAP_L2_PROMOTION_L2_128B, CU_TENSOR_MAP_FLOAT_OOB_FILL_NONE);
    return m;
}

extern "C" void kernel_launch(void* const* d_in, const int* in_sizes, int n_in,
                              void* d_out, int out_size)
{
    const float* A = (const float*)d_in[0];   // [8, 2048, 2048]
    const float* h = (const float*)d_in[1];   // [9, 64]
    float* out = (float*)d_out;               // [8, 2048, 64]

    void *A2, *A3, *A4, *Ah, *Al, *AhT, *AlT, *A2h, *A2l, *A2hT, *A2lT;
    cudaGetSymbolAddress(&A2, g_A2);   cudaGetSymbolAddress(&A3, g_A3);
    cudaGetSymbolAddress(&A4, g_A4);
    cudaGetSymbolAddress(&Ah, g_Ah);   cudaGetSymbolAddress(&Al, g_Al);
    cudaGetSymbolAddress(&AhT, g_AhT); cudaGetSymbolAddress(&AlT, g_AlT);
    cudaGetSymbolAddress(&A2h, g_A2h); cudaGetSymbolAddress(&A2l, g_A2l);
    cudaGetSymbolAddress(&A2hT, g_A2hT); cudaGetSymbolAddress(&A2lT, g_A2lT);

    PFN_tmap_encode enc = nullptr;
    {
        void* fn = nullptr;
        cudaDriverEntryPointQueryResult qr;
        cudaGetDriverEntryPoint("cuTensorMapEncodeTiled", &fn,
                                cudaEnableDefault, &qr);
        enc = (PFN_tmap_encode)fn;
    }
    if (!enc) return;

    const CUtensorMap mAh   = make_map(enc, Ah,   BM);
    const CUtensorMap mAl   = make_map(enc, Al,   BM);
    const CUtensorMap mAhT  = make_map(enc, AhT,  BN);
    const CUtensorMap mAlT  = make_map(enc, AlT,  BN);
    const CUtensorMap mA2h  = make_map(enc, A2h,  BM);
    const CUtensorMap mA2l  = make_map(enc, A2l,  BM);
    const CUtensorMap mA2hT = make_map(enc, A2hT, BN);
    const CUtensorMap mA2lT = make_map(enc, A2lT, BN);

    cudaFuncSetAttribute(gemm_tma,
                         cudaFuncAttributeMaxDynamicSharedMemorySize, SMEM_GEMM);

    split_both_kernel<<<dim3(N / 32, N / 32, NB), dim3(32, 8)>>>(
        A, (__nv_bfloat16*)Ah, (__nv_bfloat16*)Al,
        (__nv_bfloat16*)AhT, (__nv_bfloat16*)AlT);

    const dim3 gg(N / BN, N / BM, NB);
    // A2 = A @ A
    gemm_tma<<<gg, 256, SMEM_GEMM>>>(mAh, mAl, mAhT, mAlT, (float*)A2);

    split_both_kernel<<<dim3(N / 32, N / 32, NB), dim3(32, 8)>>>(
        (const float*)A2, (__nv_bfloat16*)A2h, (__nv_bfloat16*)A2l,
        (__nv_bfloat16*)A2hT, (__nv_bfloat16*)A2lT);

    // A3 = A2 @ A
    gemm_tma<<<gg, 256, SMEM_GEMM>>>(mA2h, mA2l, mAhT, mAlT, (float*)A3);
    // A4 = A2 @ A2
    gemm_tma<<<gg, 256, SMEM_GEMM>>>(mA2h, mA2l, mA2hT, mA2lT, (float*)A4);

    diag_kernel<<<dim3(N / 32, NB), 256>>>(A);

    const int total = NB * N * 64;
    combine_kernel<<<(total + 255) / 256, 256>>>(A, h, out);
}